// round 8
// baseline (speedup 1.0000x reference)
#include <cuda_runtime.h>
#include <cuda_fp16.h>
#include <cstdint>

// ---------------------------------------------------------------------------
// B=2,S=2048,D=1024,H=16,HD=64, scale=32. softmax over batch (B=2) ==
//   P     = sigmoid((Q0K0^T - Q1K1^T)/32)   per head [2048x2048]
//   vals0 = P @ V0 ;  vals1 = colsum(V1) - P @ V1
// fp16 mma.sync m16n8k16 NT GEMMs, hi/lo split planes:
//   Q/K proj, score: 3-term | V proj, out: 2-term | PV: 1-term
// ---------------------------------------------------------------------------

__device__ __align__(128) __half g_xhi[4096 * 1024];
__device__ __align__(128) __half g_xlo[4096 * 1024];
__device__ __align__(128) __half g_wThi[4 * 1024 * 1024];   // [z][n][k]
__device__ __align__(128) __half g_wTlo[4 * 1024 * 1024];
__device__ __align__(128) __half g_Qhi[16 * 2048 * 128];    // [h][s][b*64+d]
__device__ __align__(128) __half g_Qlo[16 * 2048 * 128];
__device__ __align__(128) __half g_Khi[16 * 2048 * 128];    // K1 negated
__device__ __align__(128) __half g_Klo[16 * 2048 * 128];
__device__ __align__(128) __half g_V16[16 * 2048 * 128];    // fp16 V [h][s][b*64+d]
__device__ __align__(128) __half g_Vthi[16 * 128 * 2048];   // [h][b*64+d][s]
__device__ __align__(128) __half g_P[(size_t)16 * 2048 * 2048];
__device__ __align__(128) __half g_Valshi[4096 * 1024];     // [b*2048+q][h*64+d]
__device__ float g_ColPart[16 * 16 * 64];
__device__ float g_Colsum[16 * 64];

#define SSTR 40                  // halfs/row for K32 chunks (32 + 8 pad)
#define APL  (128 * SSTR)        // A plane: 5120 halfs
#define BPL  (64 * SSTR)         // B plane: 2560 halfs
#define QSTR 136                 // halfs/row resident Q (128 + 8 pad)

// ---------------------------------------------------------------------------
static __device__ __forceinline__ void cpa16(const __half* dst_smem, const void* src) {
    uint32_t d = (uint32_t)__cvta_generic_to_shared(dst_smem);
    asm volatile("cp.async.cg.shared.global [%0], [%1], 16;" :: "r"(d), "l"(src));
}
static __device__ __forceinline__ void ldm4(uint32_t r[4], const __half* p) {
    uint32_t a = (uint32_t)__cvta_generic_to_shared(p);
    asm volatile("ldmatrix.sync.aligned.m8n8.x4.shared.b16 {%0,%1,%2,%3}, [%4];"
                 : "=r"(r[0]), "=r"(r[1]), "=r"(r[2]), "=r"(r[3]) : "r"(a));
}
static __device__ __forceinline__ void mma16816(float c[4], const uint32_t a[4],
                                                uint32_t b0, uint32_t b1) {
    asm volatile(
        "mma.sync.aligned.m16n8k16.row.col.f32.f16.f16.f32 "
        "{%0,%1,%2,%3}, {%4,%5,%6,%7}, {%8,%9}, {%0,%1,%2,%3};"
        : "+f"(c[0]), "+f"(c[1]), "+f"(c[2]), "+f"(c[3])
        : "r"(a[0]), "r"(a[1]), "r"(a[2]), "r"(a[3]), "r"(b0), "r"(b1));
}
static __device__ __forceinline__ void splitstore(__half* hp, __half* lp,
                                                  float v0, float v1) {
    __half h0 = __float2half_rn(v0), h1 = __float2half_rn(v1);
    *(__half2*)hp = __halves2half2(h0, h1);
    *(__half2*)lp = __halves2half2(__float2half_rn(v0 - __half2float(h0)),
                                   __float2half_rn(v1 - __half2float(h1)));
}

enum { EPI_QK = 0, EPI_V, EPI_PV, EPI_OUT };

// ---------------------------------------------------------------------------
// 128x64 NT GEMM tile, fp16 mma + ldmatrix, 3-stage cp.async, occ 2.
// NTERM=3: Ahi*Bhi + Ahi*Blo + Alo*Bhi ; 2: A*(Bhi+Blo) ; 1: A*B
// 8 warps = 4m x 2n; warp 32x32; acc c[2][4][4].
// ---------------------------------------------------------------------------
template <int KTOT, int NTERM, int EPI>
__global__ __launch_bounds__(256, 2) void gemm_kernel(float* outp)
{
    extern __shared__ __align__(128) __half sm[];
    const int NA = (NTERM == 3) ? 2 : 1;
    const int NB = (NTERM == 1) ? 1 : 2;
    const int STG = NA * APL + NB * BPL;

    const int tid = threadIdx.x, warp = tid >> 5, lane = tid & 31;
    const int wm = (warp & 3) * 32, wn = (warp >> 2) * 32;
    const int m0 = blockIdx.y * 128, n0 = blockIdx.x * 64, z = blockIdx.z;

    const __half *Ahi, *Alo = nullptr, *Bhi, *Blo = nullptr;
    int lda, ldb;
    if (EPI == EPI_QK) {
        Ahi = g_xhi; Alo = g_xlo; lda = 1024;
        Bhi = g_wThi + (size_t)z * 1048576; Blo = g_wTlo + (size_t)z * 1048576; ldb = 1024;
    } else if (EPI == EPI_V) {
        Ahi = g_xhi; lda = 1024;
        Bhi = g_wThi + (size_t)2 * 1048576; Blo = g_wTlo + (size_t)2 * 1048576; ldb = 1024;
    } else if (EPI == EPI_PV) {
        Ahi = g_P + (size_t)z * 2048 * 2048; lda = 2048;
        Bhi = g_Vthi + (size_t)z * 128 * 2048; ldb = 2048;
    } else {
        Ahi = g_Valshi; lda = 1024;
        Bhi = g_wThi + (size_t)3 * 1048576; Blo = g_wTlo + (size_t)3 * 1048576; ldb = 1024;
    }

    auto aplane = [&](int st, int pl) -> __half* { return sm + st * STG + pl * APL; };
    auto bplane = [&](int st, int pl) -> __half* { return sm + st * STG + NA * APL + pl * BPL; };

    auto load_stage = [&](int ch) {
        const int st = ch % 3, k0 = ch * 32;
#pragma unroll
        for (int r = 0; r < 2; ++r) {           // A: 512 x 16B
            const int idx = tid + r * 256;
            const int row = idx >> 2, col = (idx & 3) * 8;
            cpa16(aplane(st, 0) + row * SSTR + col, Ahi + (size_t)(m0 + row) * lda + k0 + col);
            if (NA == 2)
                cpa16(aplane(st, 1) + row * SSTR + col, Alo + (size_t)(m0 + row) * lda + k0 + col);
        }
        {                                        // B: 256 x 16B per plane
            const int row = tid >> 2, col = (tid & 3) * 8;
            cpa16(bplane(st, 0) + row * SSTR + col, Bhi + (size_t)(n0 + row) * ldb + k0 + col);
            if (NB == 2)
                cpa16(bplane(st, 1) + row * SSTR + col, Blo + (size_t)(n0 + row) * ldb + k0 + col);
        }
        asm volatile("cp.async.commit_group;" ::: "memory");
    };

    float c[2][4][4] = {};
    const int nCh = KTOT / 32;
    load_stage(0);
    if (nCh > 1) load_stage(1);

    const int lrow = lane & 15, lkh = (lane >> 4) * 8;

    for (int ch = 0; ch < nCh; ++ch) {
        if (ch + 1 < nCh) asm volatile("cp.async.wait_group 1;" ::: "memory");
        else              asm volatile("cp.async.wait_group 0;" ::: "memory");
        __syncthreads();
        if (ch + 2 < nCh) load_stage(ch + 2);
        const int st = ch % 3;

#pragma unroll
        for (int s = 0; s < 2; ++s) {
            const int ks = s * 16;
            uint32_t a[2][2][4];
#pragma unroll
            for (int pa = 0; pa < NA; ++pa)
#pragma unroll
                for (int mt = 0; mt < 2; ++mt)
                    ldm4(a[pa][mt], aplane(st, pa) + (wm + mt * 16 + lrow) * SSTR + ks + lkh);
            uint32_t bh[2][4], bl[2][4];
#pragma unroll
            for (int np = 0; np < 2; ++np)
                ldm4(bh[np], bplane(st, 0) + (wn + np * 16 + lrow) * SSTR + ks + lkh);
            if (NB == 2)
#pragma unroll
                for (int np = 0; np < 2; ++np)
                    ldm4(bl[np], bplane(st, 1) + (wn + np * 16 + lrow) * SSTR + ks + lkh);

#pragma unroll
            for (int np = 0; np < 2; ++np)
#pragma unroll
                for (int mt = 0; mt < 2; ++mt) {
                    mma16816(c[mt][2 * np],     a[0][mt], bh[np][0], bh[np][2]);
                    mma16816(c[mt][2 * np + 1], a[0][mt], bh[np][1], bh[np][3]);
                }
            if (NB == 2)
#pragma unroll
                for (int np = 0; np < 2; ++np)
#pragma unroll
                    for (int mt = 0; mt < 2; ++mt) {
                        mma16816(c[mt][2 * np],     a[0][mt], bl[np][0], bl[np][2]);
                        mma16816(c[mt][2 * np + 1], a[0][mt], bl[np][1], bl[np][3]);
                    }
            if (NA == 2)
#pragma unroll
                for (int np = 0; np < 2; ++np)
#pragma unroll
                    for (int mt = 0; mt < 2; ++mt) {
                        mma16816(c[mt][2 * np],     a[1][mt], bh[np][0], bh[np][2]);
                        mma16816(c[mt][2 * np + 1], a[1][mt], bh[np][1], bh[np][3]);
                    }
        }
    }

    // ---- epilogue: m = m0+wm+mt*16+lane/4+p*8 ; n = n0+wn+nt*8+(lane%4)*2 ----
#pragma unroll
    for (int mt = 0; mt < 2; ++mt)
#pragma unroll
        for (int nt = 0; nt < 4; ++nt)
#pragma unroll
            for (int p = 0; p < 2; ++p) {
                const int m = m0 + wm + mt * 16 + (lane >> 2) + p * 8;
                const int nl = wn + nt * 8 + (lane & 3) * 2;
                float v0 = c[mt][nt][2 * p], v1 = c[mt][nt][2 * p + 1];

                if (EPI == EPI_QK) {
                    const int b = m >> 11, s = m & 2047;
                    const int n = n0 + nl, h = n >> 6, d = n & 63;
                    const size_t base = ((size_t)(h * 2048 + s)) * 128 + b * 64 + d;
                    if (z == 1 && b == 1) { v0 = -v0; v1 = -v1; }
                    __half* Dh = (z == 0) ? g_Qhi : g_Khi;
                    __half* Dl = (z == 0) ? g_Qlo : g_Klo;
                    splitstore(&Dh[base], &Dl[base], v0, v1);
                } else if (EPI == EPI_V) {
                    const int b = m >> 11, s = m & 2047;
                    const int n = n0 + nl, h = n >> 6, d = n & 63;
                    *(__half2*)&g_V16[((size_t)(h * 2048 + s)) * 128 + b * 64 + d] =
                        __floats2half2_rn(v0, v1);
                } else if (EPI == EPI_PV) {
                    const int n = n0 + nl, b = n >> 6, d = n & 63;
                    if (b) {
                        v0 = g_Colsum[z * 64 + d]     - v0;
                        v1 = g_Colsum[z * 64 + d + 1] - v1;
                    }
                    *(__half2*)&g_Valshi[((size_t)(b * 2048 + m)) * 1024 + z * 64 + d] =
                        __floats2half2_rn(v0, v1);
                } else {
                    *(float2*)&outp[(size_t)m * 1024 + n0 + nl] = make_float2(v0, v1);
                }
            }
}

// ---------------------------------------------------------------------------
// Score: M=64 Q hi/lo resident; stream K hi/lo over 16 n-tiles x 4 K32-chunks.
// occ 2 (96 KB smem). 8 warps = 2m x 4n; warp 32x32.
// Grid (1, 32, 16) = (.., m-tile, head).
// ---------------------------------------------------------------------------
__global__ __launch_bounds__(256, 2) void score_kernel()
{
    extern __shared__ __align__(128) __half sm[];
    __half* Q0 = sm;                       // 64 x QSTR
    __half* Q1 = sm + 64 * QSTR;
    __half* Bb = sm + 2 * 64 * QSTR;       // 3 stages x 2 planes x 128 x SSTR
    auto bpl = [&](int st, int pl) -> __half* { return Bb + (st * 2 + pl) * (128 * SSTR); };

    const int tid = threadIdx.x, warp = tid >> 5, lane = tid & 31;
    const int wm = (warp & 1) * 32, wn = (warp >> 1) * 32;
    const int h = blockIdx.z, m0 = blockIdx.y * 64;

    const __half* Qh = g_Qhi + (size_t)h * 2048 * 128 + (size_t)m0 * 128;
    const __half* Ql = g_Qlo + (size_t)h * 2048 * 128 + (size_t)m0 * 128;
    const __half* Kh = g_Khi + (size_t)h * 2048 * 128;
    const __half* Kl = g_Klo + (size_t)h * 2048 * 128;

    // resident Q: 64 x 128 per plane
#pragma unroll
    for (int r = 0; r < 4; ++r) {
        const int idx = tid + r * 256;
        const int row = idx >> 4, col = (idx & 15) * 8;
        cpa16(Q0 + row * QSTR + col, Qh + row * 128 + col);
        cpa16(Q1 + row * QSTR + col, Ql + row * 128 + col);
    }
    asm volatile("cp.async.commit_group;" ::: "memory");

    auto loadB = [&](int g) {
        const int st = g % 3, ntl = g >> 2, k0 = (g & 3) * 32;
#pragma unroll
        for (int r = 0; r < 2; ++r) {
            const int idx = tid + r * 256;
            const int row = idx >> 2, col = (idx & 3) * 8;
            const size_t src = (size_t)(ntl * 128 + row) * 128 + k0 + col;
            cpa16(bpl(st, 0) + row * SSTR + col, Kh + src);
            cpa16(bpl(st, 1) + row * SSTR + col, Kl + src);
        }
        asm volatile("cp.async.commit_group;" ::: "memory");
    };

    loadB(0); loadB(1);
    float c[2][4][4] = {};
    const int lrow = lane & 15, lkh = (lane >> 4) * 8;
    const __half2 one2 = __float2half2_rn(1.0f);
    const float NK = -0.04508422f;   // -log2(e)/32

    const int G = 64;   // 16 n-tiles x 4 chunks
    for (int g = 0; g < G; ++g) {
        if (g + 1 < G) asm volatile("cp.async.wait_group 1;" ::: "memory");
        else           asm volatile("cp.async.wait_group 0;" ::: "memory");
        __syncthreads();
        if (g + 2 < G) loadB(g + 2);

        const int st = g % 3, kk = (g & 3) * 32;
#pragma unroll
        for (int s = 0; s < 2; ++s) {
            const int kq = kk + s * 16 + lkh, ks = s * 16 + lkh;
            uint32_t a[2][2][4];
#pragma unroll
            for (int mt = 0; mt < 2; ++mt) {
                ldm4(a[0][mt], Q0 + (wm + mt * 16 + lrow) * QSTR + kq);
                ldm4(a[1][mt], Q1 + (wm + mt * 16 + lrow) * QSTR + kq);
            }
            uint32_t bh[2][4], bl[2][4];
#pragma unroll
            for (int np = 0; np < 2; ++np) {
                ldm4(bh[np], bpl(st, 0) + (wn + np * 16 + lrow) * SSTR + ks);
                ldm4(bl[np], bpl(st, 1) + (wn + np * 16 + lrow) * SSTR + ks);
            }
#pragma unroll
            for (int np = 0; np < 2; ++np)
#pragma unroll
                for (int mt = 0; mt < 2; ++mt) {
                    mma16816(c[mt][2 * np],     a[0][mt], bh[np][0], bh[np][2]);
                    mma16816(c[mt][2 * np + 1], a[0][mt], bh[np][1], bh[np][3]);
                }
#pragma unroll
            for (int np = 0; np < 2; ++np)
#pragma unroll
                for (int mt = 0; mt < 2; ++mt) {
                    mma16816(c[mt][2 * np],     a[0][mt], bl[np][0], bl[np][2]);
                    mma16816(c[mt][2 * np + 1], a[0][mt], bl[np][1], bl[np][3]);
                }
#pragma unroll
            for (int np = 0; np < 2; ++np)
#pragma unroll
                for (int mt = 0; mt < 2; ++mt) {
                    mma16816(c[mt][2 * np],     a[1][mt], bh[np][0], bh[np][2]);
                    mma16816(c[mt][2 * np + 1], a[1][mt], bh[np][1], bh[np][3]);
                }
        }

        if ((g & 3) == 3) {   // epilogue for finished n-tile
            const int nb = (g >> 2) * 128;
#pragma unroll
            for (int mt = 0; mt < 2; ++mt)
#pragma unroll
                for (int nt = 0; nt < 4; ++nt)
#pragma unroll
                    for (int p = 0; p < 2; ++p) {
                        const int m = m0 + wm + mt * 16 + (lane >> 2) + p * 8;
                        const int n = nb + wn + nt * 8 + (lane & 3) * 2;
                        __half2 m2 = __floats2half2_rn(c[mt][nt][2 * p] * NK,
                                                       c[mt][nt][2 * p + 1] * NK);
                        __half2 P2 = h2rcp(__hadd2(one2, h2exp2(m2)));
                        *(__half2*)&g_P[((size_t)h * 2048 + m) * 2048 + n] = P2;
                        c[mt][nt][2 * p] = 0.f; c[mt][nt][2 * p + 1] = 0.f;
                    }
        }
    }
}

// ---------------------------------------------------------------------------
// prep kernels
// ---------------------------------------------------------------------------
__global__ __launch_bounds__(256) void split_x_kernel(const float* __restrict__ x)
{
    const size_t i = ((size_t)blockIdx.x * 256 + threadIdx.x) * 4;
    float4 v = *(const float4*)(x + i);
    splitstore(&g_xhi[i],     &g_xlo[i],     v.x, v.y);
    splitstore(&g_xhi[i + 2], &g_xlo[i + 2], v.z, v.w);
}

__global__ __launch_bounds__(256) void trw_kernel(
    const float* __restrict__ w0, const float* __restrict__ w1,
    const float* __restrict__ w2, const float* __restrict__ w3)
{
    const float* W = (blockIdx.z == 0) ? w0 : (blockIdx.z == 1) ? w1
                     : (blockIdx.z == 2) ? w2 : w3;
    __shared__ float t[32][33];
    const int bx = blockIdx.x * 32, by = blockIdx.y * 32;
    const int tx = threadIdx.x & 31, ty8 = threadIdx.x >> 5;
#pragma unroll
    for (int s = 0; s < 4; ++s)
        t[ty8 + s * 8][tx] = W[(size_t)(by + ty8 + s * 8) * 1024 + bx + tx];
    __syncthreads();
    __half* Dh = g_wThi + (size_t)blockIdx.z * 1048576;
    __half* Dl = g_wTlo + (size_t)blockIdx.z * 1048576;
#pragma unroll
    for (int s = 0; s < 4; ++s) {
        const int ty = ty8 + s * 8;
        const float v = t[tx][ty];
        const size_t o = (size_t)(bx + ty) * 1024 + by + tx;
        __half h = __float2half_rn(v);
        Dh[o] = h;
        Dl[o] = __float2half_rn(v - __half2float(h));
    }
}

// transpose V per (head, 128-s-chunk) + deterministic colsum partials of V1
__global__ __launch_bounds__(256) void trv_kernel()
{
    extern __shared__ float tl[];   // [128][129]
    const int sc = blockIdx.x, h = blockIdx.y;
    const int s0 = sc * 128;
    const __half* V = g_V16 + ((size_t)h * 2048 + s0) * 128;

    for (int i = threadIdx.x; i < 128 * 128; i += 256)
        tl[(i >> 7) * 129 + (i & 127)] = __half2float(V[i]);
    __syncthreads();

    if (threadIdx.x < 64) {
        float acc = 0.f;
        for (int s = 0; s < 128; ++s) acc += tl[s * 129 + 64 + threadIdx.x];
        g_ColPart[((size_t)h * 16 + sc) * 64 + threadIdx.x] = acc;
    }

    const int dp = threadIdx.x & 127, seg = threadIdx.x >> 7;
    __half* Th = g_Vthi + ((size_t)h * 128 + dp) * 2048 + s0 + seg * 64;
#pragma unroll 8
    for (int j = 0; j < 64; ++j)
        Th[j] = __float2half_rn(tl[(seg * 64 + j) * 129 + dp]);
}

__global__ void redc_kernel()
{
    const int t = threadIdx.x;   // 1024 = 16h * 64d
    const int h = t >> 6, d = t & 63;
    float a = 0.f;
    for (int sc = 0; sc < 16; ++sc)
        a += g_ColPart[((size_t)h * 16 + sc) * 64 + d];
    g_Colsum[t] = a;
}

// ---------------------------------------------------------------------------
extern "C" void kernel_launch(void* const* d_in, const int* in_sizes, int n_in,
                              void* d_out, int out_size)
{
    const float* x  = (const float*)d_in[0];
    const float* wq = (const float*)d_in[1];
    const float* wk = (const float*)d_in[2];
    const float* wv = (const float*)d_in[3];
    const float* wo = (const float*)d_in[4];
    float* out = (float*)d_out;

    const int SM_QK = (2 * APL + 2 * BPL) * 3 * 2;        // 92160
    const int SM_V  = (1 * APL + 2 * BPL) * 3 * 2;        // 61440
    const int SM_PV = (1 * APL + 1 * BPL) * 3 * 2;        // 46080
    const int SM_SC = (2 * 64 * QSTR + 3 * 2 * 128 * SSTR) * 2;  // 96256
    const int SMT   = 128 * 129 * 4;                      // 66048

    cudaFuncSetAttribute(gemm_kernel<1024, 3, EPI_QK>,  cudaFuncAttributeMaxDynamicSharedMemorySize, SM_QK);
    cudaFuncSetAttribute(gemm_kernel<1024, 2, EPI_V>,   cudaFuncAttributeMaxDynamicSharedMemorySize, SM_V);
    cudaFuncSetAttribute(gemm_kernel<2048, 1, EPI_PV>,  cudaFuncAttributeMaxDynamicSharedMemorySize, SM_PV);
    cudaFuncSetAttribute(gemm_kernel<1024, 2, EPI_OUT>, cudaFuncAttributeMaxDynamicSharedMemorySize, SM_V);
    cudaFuncSetAttribute(score_kernel, cudaFuncAttributeMaxDynamicSharedMemorySize, SM_SC);
    cudaFuncSetAttribute(trv_kernel,   cudaFuncAttributeMaxDynamicSharedMemorySize, SMT);

    split_x_kernel<<<4096, 256>>>(x);
    trw_kernel<<<dim3(32, 32, 4), 256>>>(wq, wk, wv, wo);

    gemm_kernel<1024, 3, EPI_QK><<<dim3(16, 32, 2), 256, SM_QK>>>(nullptr);
    gemm_kernel<1024, 2, EPI_V><<<dim3(16, 32, 1), 256, SM_V>>>(nullptr);

    trv_kernel<<<dim3(16, 16), 256, SMT>>>();
    redc_kernel<<<1, 1024>>>();

    score_kernel<<<dim3(1, 32, 16), 256, SM_SC>>>();
    gemm_kernel<2048, 1, EPI_PV><<<dim3(2, 16, 16), 256, SM_PV>>>(nullptr);
    gemm_kernel<1024, 2, EPI_OUT><<<dim3(16, 32, 1), 256, SM_V>>>(out);
}

// round 10
// speedup vs baseline: 1.1339x; 1.1339x over previous
#include <cuda_runtime.h>
#include <cuda_fp16.h>
#include <cstdint>

// ---------------------------------------------------------------------------
// B=2,S=2048,D=1024,H=16,HD=64, scale=32. softmax over batch (B=2) ==
//   P     = sigmoid((Q0K0^T - Q1K1^T)/32)   per head [2048x2048]
//   vals0 = P @ V0 ;  vals1 = colsum(V1) - P @ V1
// fp16 mma.sync m16n8k16 NT GEMMs; hi/lo split planes:
//   Q/K proj, score: 3-term | out: 2-term | V proj, PV: 1-term
// ---------------------------------------------------------------------------

__device__ __align__(128) __half g_xhi[4096 * 1024];
__device__ __align__(128) __half g_xlo[4096 * 1024];
__device__ __align__(128) __half g_wThi[4 * 1024 * 1024];   // [z][n][k]
__device__ __align__(128) __half g_wTlo[4 * 1024 * 1024];
__device__ __align__(128) __half g_Qhi[16 * 2048 * 128];    // [h][s][b*64+d]
__device__ __align__(128) __half g_Qlo[16 * 2048 * 128];
__device__ __align__(128) __half g_Khi[16 * 2048 * 128];    // K1 negated
__device__ __align__(128) __half g_Klo[16 * 2048 * 128];
__device__ __align__(128) __half g_V16[16 * 2048 * 128];    // fp16 V [h][s][b*64+d]
__device__ __align__(128) __half g_Vthi[16 * 128 * 2048];   // [h][b*64+d][s]
__device__ __align__(128) __half g_P[(size_t)16 * 2048 * 2048];
__device__ __align__(128) __half g_Valshi[4096 * 1024];     // [b*2048+q][h*64+d]
__device__ float g_ColPart[16 * 16 * 64];
__device__ float g_Colsum[16 * 64];

#define SSTR   40                 // halfs per smem row, 32-K chunks (+8 pad)
#define PLANEH (128 * SSTR)       // 5120 halfs / 10240 B
#define ASTR   136                // halfs per row for resident 128-K planes

// ---------------------------------------------------------------------------
static __device__ __forceinline__ void cpa16(const __half* dst_smem, const void* src) {
    uint32_t d = (uint32_t)__cvta_generic_to_shared(dst_smem);
    asm volatile("cp.async.cg.shared.global [%0], [%1], 16;" :: "r"(d), "l"(src));
}
static __device__ __forceinline__ void ldm4(uint32_t r[4], const __half* p) {
    uint32_t a = (uint32_t)__cvta_generic_to_shared(p);
    asm volatile("ldmatrix.sync.aligned.m8n8.x4.shared.b16 {%0,%1,%2,%3}, [%4];"
                 : "=r"(r[0]), "=r"(r[1]), "=r"(r[2]), "=r"(r[3]) : "r"(a));
}
static __device__ __forceinline__ void mma16816(float c[4], const uint32_t a[4],
                                                uint32_t b0, uint32_t b1) {
    asm volatile(
        "mma.sync.aligned.m16n8k16.row.col.f32.f16.f16.f32 "
        "{%0,%1,%2,%3}, {%4,%5,%6,%7}, {%8,%9}, {%0,%1,%2,%3};"
        : "+f"(c[0]), "+f"(c[1]), "+f"(c[2]), "+f"(c[3])
        : "r"(a[0]), "r"(a[1]), "r"(a[2]), "r"(a[3]), "r"(b0), "r"(b1));
}
static __device__ __forceinline__ void splitstore(__half* hp, __half* lp,
                                                  float v0, float v1) {
    __half h0 = __float2half_rn(v0), h1 = __float2half_rn(v1);
    *(__half2*)hp = __halves2half2(h0, h1);
    *(__half2*)lp = __halves2half2(__float2half_rn(v0 - __half2float(h0)),
                                   __float2half_rn(v1 - __half2float(h1)));
}

enum { EPI_QK = 0, EPI_V, EPI_PV, EPI_OUT };

// ---------------------------------------------------------------------------
// 128x128 NT GEMM, fp16 mma + ldmatrix, NSTG-stage cp.async, fused epilogue.
// NTERM=3: Ahi*Bhi + Alo*Bhi + Ahi*Blo ; NTERM=2: A*(Bhi+Blo) ; NTERM=1: A*Bhi
// B-hi fragments are loaded once and reused across terms.
// ---------------------------------------------------------------------------
template <int KTOT, int NTERM, int EPI, int OCC, int NSTG>
__global__ __launch_bounds__(256, OCC) void gemm_kernel(float* outp)
{
    extern __shared__ __align__(128) __half sm[];
    const int NA = (NTERM == 3) ? 2 : 1;
    const int NB = (NTERM >= 2) ? 2 : 1;
    const int NT = NA + NB;

    const int tid = threadIdx.x, warp = tid >> 5, lane = tid & 31;
    const int wm = (warp & 3) * 32, wn = (warp >> 2) * 64;
    const int m0 = blockIdx.y * 128, n0 = blockIdx.x * 128, z = blockIdx.z;

    const __half *Ahi, *Alo = nullptr, *Bhi, *Blo = nullptr;
    int lda, ldb;
    if (EPI == EPI_QK) {
        Ahi = g_xhi; Alo = g_xlo; lda = 1024;
        Bhi = g_wThi + (size_t)z * 1048576; Blo = g_wTlo + (size_t)z * 1048576; ldb = 1024;
    } else if (EPI == EPI_V) {
        Ahi = g_xhi; lda = 1024;
        Bhi = g_wThi + (size_t)2 * 1048576; ldb = 1024;
    } else if (EPI == EPI_PV) {
        Ahi = g_P + (size_t)z * 2048 * 2048; lda = 2048;
        Bhi = g_Vthi + (size_t)z * 128 * 2048; ldb = 2048;
    } else {
        Ahi = g_Valshi; lda = 1024;
        Bhi = g_wThi + (size_t)3 * 1048576; Blo = g_wTlo + (size_t)3 * 1048576; ldb = 1024;
    }

    auto plane = [&](int st, int pl) -> __half* { return sm + (st * NT + pl) * PLANEH; };

    auto load_stage = [&](int ch) {
        const int st = ch % NSTG, k0 = ch * 32;
#pragma unroll
        for (int r = 0; r < 2; ++r) {
            const int idx = tid + r * 256;
            const int row = idx >> 2, col = (idx & 3) * 8;
            cpa16(plane(st, 0) + row * SSTR + col, Ahi + (size_t)(m0 + row) * lda + k0 + col);
            if (NA == 2)
                cpa16(plane(st, 1) + row * SSTR + col, Alo + (size_t)(m0 + row) * lda + k0 + col);
            cpa16(plane(st, NA) + row * SSTR + col, Bhi + (size_t)(n0 + row) * ldb + k0 + col);
            if (NB == 2)
                cpa16(plane(st, NA + 1) + row * SSTR + col, Blo + (size_t)(n0 + row) * ldb + k0 + col);
        }
        asm volatile("cp.async.commit_group;" ::: "memory");
    };

    float c[2][8][4] = {};
    const int nCh = KTOT / 32;
    load_stage(0);
    if (NSTG == 3 && nCh > 1) load_stage(1);

    const int lrow = lane & 15, lkh = (lane >> 4) * 8;

    for (int ch = 0; ch < nCh; ++ch) {
        if (NSTG == 3) {
            if (ch + 1 < nCh) asm volatile("cp.async.wait_group 1;" ::: "memory");
            else              asm volatile("cp.async.wait_group 0;" ::: "memory");
            __syncthreads();
            if (ch + 2 < nCh) load_stage(ch + 2);
        } else {
            if (ch + 1 < nCh) {
                __syncthreads();
                load_stage(ch + 1);
                asm volatile("cp.async.wait_group 1;" ::: "memory");
            } else {
                asm volatile("cp.async.wait_group 0;" ::: "memory");
            }
            __syncthreads();
        }
        const int buf = ch % NSTG;

#pragma unroll
        for (int s = 0; s < 2; ++s) {
            const int ks = s * 16;
            uint32_t a[2][2][4];
#pragma unroll
            for (int pa = 0; pa < NA; ++pa)
#pragma unroll
                for (int mt = 0; mt < 2; ++mt)
                    ldm4(a[pa][mt], plane(buf, pa) + (wm + mt * 16 + lrow) * SSTR + ks + lkh);

            // B-hi fragments: load once, reuse for term 1 and (NA==2) term 2
            uint32_t bh[4][4];
#pragma unroll
            for (int np = 0; np < 4; ++np) {
                ldm4(bh[np], plane(buf, NA) + (wn + np * 16 + lrow) * SSTR + ks + lkh);
#pragma unroll
                for (int mt = 0; mt < 2; ++mt) {
                    mma16816(c[mt][2 * np],     a[0][mt], bh[np][0], bh[np][2]);
                    mma16816(c[mt][2 * np + 1], a[0][mt], bh[np][1], bh[np][3]);
                }
            }
            if (NA == 2) {
#pragma unroll
                for (int np = 0; np < 4; ++np)
#pragma unroll
                    for (int mt = 0; mt < 2; ++mt) {
                        mma16816(c[mt][2 * np],     a[1][mt], bh[np][0], bh[np][2]);
                        mma16816(c[mt][2 * np + 1], a[1][mt], bh[np][1], bh[np][3]);
                    }
            }
            if (NB == 2) {
#pragma unroll
                for (int np = 0; np < 4; ++np) {
                    uint32_t bl[4];
                    ldm4(bl, plane(buf, NA + 1) + (wn + np * 16 + lrow) * SSTR + ks + lkh);
#pragma unroll
                    for (int mt = 0; mt < 2; ++mt) {
                        mma16816(c[mt][2 * np],     a[0][mt], bl[0], bl[2]);
                        mma16816(c[mt][2 * np + 1], a[0][mt], bl[1], bl[3]);
                    }
                }
            }
        }
    }

    // ---- epilogue: m = m0+wm+mt*16+lane/4+p*8 ; n = n0+wn+nt*8+(lane%4)*2 ----
#pragma unroll
    for (int mt = 0; mt < 2; ++mt)
#pragma unroll
        for (int nt = 0; nt < 8; ++nt)
#pragma unroll
            for (int p = 0; p < 2; ++p) {
                const int m = m0 + wm + mt * 16 + (lane >> 2) + p * 8;
                const int nl = wn + nt * 8 + (lane & 3) * 2;
                float v0 = c[mt][nt][2 * p], v1 = c[mt][nt][2 * p + 1];

                if (EPI == EPI_QK) {
                    const int b = m >> 11, s = m & 2047;
                    const int n = n0 + nl, h = n >> 6, d = n & 63;
                    const size_t base = ((size_t)(h * 2048 + s)) * 128 + b * 64 + d;
                    if (z == 1 && b == 1) { v0 = -v0; v1 = -v1; }
                    __half* Dh = (z == 0) ? g_Qhi : g_Khi;
                    __half* Dl = (z == 0) ? g_Qlo : g_Klo;
                    splitstore(&Dh[base], &Dl[base], v0, v1);
                } else if (EPI == EPI_V) {
                    const int b = m >> 11, s = m & 2047;
                    const int n = n0 + nl, h = n >> 6, d = n & 63;
                    *(__half2*)&g_V16[((size_t)(h * 2048 + s)) * 128 + b * 64 + d] =
                        __floats2half2_rn(v0, v1);
                } else if (EPI == EPI_PV) {
                    const int b = nl >> 6, d = nl & 63;
                    if (b) {
                        v0 = g_Colsum[z * 64 + d]     - v0;
                        v1 = g_Colsum[z * 64 + d + 1] - v1;
                    }
                    *(__half2*)&g_Valshi[((size_t)(b * 2048 + m)) * 1024 + z * 64 + d] =
                        __floats2half2_rn(v0, v1);
                } else {
                    *(float2*)&outp[(size_t)m * 1024 + n0 + nl] = make_float2(v0, v1);
                }
            }
}

// ---------------------------------------------------------------------------
// Score: Q hi/lo resident in smem; stream K hi/lo over 4 n-tiles.
// P = sigmoid(S/32) via f16x2 ex2+rcp.  Grid (4, 16, 16) = (n-group, m, h).
// ---------------------------------------------------------------------------
__global__ __launch_bounds__(256) void score_kernel()
{
    extern __shared__ __align__(128) __half sm[];
    __half* Aq[2] = { sm, sm + 128 * ASTR };
    __half* Bb    = sm + 2 * 128 * ASTR;
    auto bplane = [&](int st, int pl) -> __half* { return Bb + (st * 2 + pl) * PLANEH; };

    const int tid = threadIdx.x, warp = tid >> 5, lane = tid & 31;
    const int wm = (warp & 3) * 32, wn = (warp >> 2) * 64;
    const int h = blockIdx.z, m0 = blockIdx.y * 128, nb = blockIdx.x * 512;

    const __half* Qh = g_Qhi + (size_t)h * 2048 * 128 + (size_t)m0 * 128;
    const __half* Ql = g_Qlo + (size_t)h * 2048 * 128 + (size_t)m0 * 128;
    const __half* Kh = g_Khi + (size_t)h * 2048 * 128;
    const __half* Kl = g_Klo + (size_t)h * 2048 * 128;

    // resident A: 128x128 per plane (8 rounds x 16B x 2 planes)
#pragma unroll
    for (int r = 0; r < 8; ++r) {
        const int idx = tid + r * 256;
        const int row = idx >> 4, col = (idx & 15) * 8;
        cpa16(Aq[0] + row * ASTR + col, Qh + row * 128 + col);
        cpa16(Aq[1] + row * ASTR + col, Ql + row * 128 + col);
    }
    asm volatile("cp.async.commit_group;" ::: "memory");

    auto loadB = [&](int g) {
        const int st = g % 3, ntl = g >> 2, k0 = (g & 3) * 32;
#pragma unroll
        for (int r = 0; r < 2; ++r) {
            const int idx = tid + r * 256;
            const int row = idx >> 2, col = (idx & 3) * 8;
            const size_t src = (size_t)(nb + ntl * 128 + row) * 128 + k0 + col;
            cpa16(bplane(st, 0) + row * SSTR + col, Kh + src);
            cpa16(bplane(st, 1) + row * SSTR + col, Kl + src);
        }
        asm volatile("cp.async.commit_group;" ::: "memory");
    };

    loadB(0); loadB(1);
    float c[2][8][4] = {};
    const int lrow = lane & 15, lkh = (lane >> 4) * 8;
    const __half2 one2 = __float2half2_rn(1.0f);
    const float NK = -0.04508422f;   // -log2(e)/32

    const int G = 16;   // 4 n-tiles x 4 chunks
    for (int g = 0; g < G; ++g) {
        if (g + 1 < G) asm volatile("cp.async.wait_group 1;" ::: "memory");
        else           asm volatile("cp.async.wait_group 0;" ::: "memory");
        __syncthreads();
        if (g + 2 < G) loadB(g + 2);

        const int st = g % 3, ch = g & 3;
#pragma unroll
        for (int s = 0; s < 2; ++s) {
            const int kA = ch * 32 + s * 16 + lkh;
            const int ks = s * 16;
            uint32_t a[2][2][4];
#pragma unroll
            for (int pa = 0; pa < 2; ++pa)
#pragma unroll
                for (int mt = 0; mt < 2; ++mt)
                    ldm4(a[pa][mt], Aq[pa] + (wm + mt * 16 + lrow) * ASTR + kA);

            // K-hi fragments loaded once, reused for Q-hi and Q-lo terms
            uint32_t bh[4][4];
#pragma unroll
            for (int np = 0; np < 4; ++np) {
                ldm4(bh[np], bplane(st, 0) + (wn + np * 16 + lrow) * SSTR + ks + lkh);
#pragma unroll
                for (int mt = 0; mt < 2; ++mt) {
                    mma16816(c[mt][2 * np],     a[0][mt], bh[np][0], bh[np][2]);
                    mma16816(c[mt][2 * np + 1], a[0][mt], bh[np][1], bh[np][3]);
                }
            }
#pragma unroll
            for (int np = 0; np < 4; ++np)
#pragma unroll
                for (int mt = 0; mt < 2; ++mt) {
                    mma16816(c[mt][2 * np],     a[1][mt], bh[np][0], bh[np][2]);
                    mma16816(c[mt][2 * np + 1], a[1][mt], bh[np][1], bh[np][3]);
                }
#pragma unroll
            for (int np = 0; np < 4; ++np) {
                uint32_t bl[4];
                ldm4(bl, bplane(st, 1) + (wn + np * 16 + lrow) * SSTR + ks + lkh);
#pragma unroll
                for (int mt = 0; mt < 2; ++mt) {
                    mma16816(c[mt][2 * np],     a[0][mt], bl[0], bl[2]);
                    mma16816(c[mt][2 * np + 1], a[0][mt], bl[1], bl[3]);
                }
            }
        }

        if (ch == 3) {   // epilogue for finished n-tile
            const int ntl = g >> 2;
#pragma unroll
            for (int mt = 0; mt < 2; ++mt)
#pragma unroll
                for (int nt = 0; nt < 8; ++nt)
#pragma unroll
                    for (int p = 0; p < 2; ++p) {
                        const int m = m0 + wm + mt * 16 + (lane >> 2) + p * 8;
                        const int n = nb + ntl * 128 + wn + nt * 8 + (lane & 3) * 2;
                        __half2 m2 = __floats2half2_rn(c[mt][nt][2 * p] * NK,
                                                       c[mt][nt][2 * p + 1] * NK);
                        __half2 P2 = h2rcp(__hadd2(one2, h2exp2(m2)));
                        *(__half2*)&g_P[((size_t)h * 2048 + m) * 2048 + n] = P2;
                        c[mt][nt][2 * p] = 0.f; c[mt][nt][2 * p + 1] = 0.f;
                    }
        }
    }
}

// ---------------------------------------------------------------------------
// prep kernels
// ---------------------------------------------------------------------------
__global__ __launch_bounds__(256) void split_x_kernel(const float* __restrict__ x)
{
    const size_t i = ((size_t)blockIdx.x * 256 + threadIdx.x) * 4;
    float4 v = *(const float4*)(x + i);
    splitstore(&g_xhi[i],     &g_xlo[i],     v.x, v.y);
    splitstore(&g_xhi[i + 2], &g_xlo[i + 2], v.z, v.w);
}

__global__ __launch_bounds__(256) void trw_kernel(
    const float* __restrict__ w0, const float* __restrict__ w1,
    const float* __restrict__ w2, const float* __restrict__ w3)
{
    const float* W = (blockIdx.z == 0) ? w0 : (blockIdx.z == 1) ? w1
                     : (blockIdx.z == 2) ? w2 : w3;
    __shared__ float t[32][33];
    const int bx = blockIdx.x * 32, by = blockIdx.y * 32;
    const int tx = threadIdx.x & 31, ty8 = threadIdx.x >> 5;
#pragma unroll
    for (int s = 0; s < 4; ++s)
        t[ty8 + s * 8][tx] = W[(size_t)(by + ty8 + s * 8) * 1024 + bx + tx];
    __syncthreads();
    __half* Dh = g_wThi + (size_t)blockIdx.z * 1048576;
    __half* Dl = g_wTlo + (size_t)blockIdx.z * 1048576;
#pragma unroll
    for (int s = 0; s < 4; ++s) {
        const int ty = ty8 + s * 8;
        const float v = t[tx][ty];
        const size_t o = (size_t)(bx + ty) * 1024 + by + tx;
        __half h = __float2half_rn(v);
        Dh[o] = h;
        Dl[o] = __float2half_rn(v - __half2float(h));
    }
}

// transpose V per (head, 128-s-chunk) + deterministic colsum partials of V1
__global__ __launch_bounds__(256) void trv_kernel()
{
    extern __shared__ float tl[];   // [128][129]
    const int sc = blockIdx.x, h = blockIdx.y;
    const int s0 = sc * 128;
    const __half* V = g_V16 + ((size_t)h * 2048 + s0) * 128;

    for (int i = threadIdx.x; i < 128 * 128; i += 256)
        tl[(i >> 7) * 129 + (i & 127)] = __half2float(V[i]);
    __syncthreads();

    if (threadIdx.x < 64) {
        float acc = 0.f;
        for (int s = 0; s < 128; ++s) acc += tl[s * 129 + 64 + threadIdx.x];
        g_ColPart[((size_t)h * 16 + sc) * 64 + threadIdx.x] = acc;
    }

    const int dp = threadIdx.x & 127, seg = threadIdx.x >> 7;
    __half* Th = g_Vthi + ((size_t)h * 128 + dp) * 2048 + s0 + seg * 64;
#pragma unroll 8
    for (int j = 0; j < 64; ++j)
        Th[j] = __float2half_rn(tl[(seg * 64 + j) * 129 + dp]);
}

__global__ void redc_kernel()
{
    const int t = threadIdx.x;   // 1024 = 16h * 64d
    const int h = t >> 6, d = t & 63;
    float a = 0.f;
    for (int sc = 0; sc < 16; ++sc)
        a += g_ColPart[((size_t)h * 16 + sc) * 64 + d];
    g_Colsum[t] = a;
}

// ---------------------------------------------------------------------------
extern "C" void kernel_launch(void* const* d_in, const int* in_sizes, int n_in,
                              void* d_out, int out_size)
{
    const float* x  = (const float*)d_in[0];
    const float* wq = (const float*)d_in[1];
    const float* wk = (const float*)d_in[2];
    const float* wv = (const float*)d_in[3];
    const float* wo = (const float*)d_in[4];
    float* out = (float*)d_out;

    const int PB    = PLANEH * 2;                         // 10240 B / plane
    const int SM_QK = 2 * 4 * PB;                         //  81920 (3-term, 2-stage)
    const int SM_2T = 3 * 3 * PB;                         //  92160 (2-term, 3-stage)
    const int SM_1T = 3 * 2 * PB;                         //  61440 (1-term, 3-stage)
    const int SM_SC = 2 * 128 * ASTR * 2 + 3 * 2 * PB;    // 131072 (score)
    const int SMT   = 128 * 129 * 4;                      //  66048

    cudaFuncSetAttribute(gemm_kernel<1024, 3, EPI_QK,  2, 2>, cudaFuncAttributeMaxDynamicSharedMemorySize, SM_QK);
    cudaFuncSetAttribute(gemm_kernel<1024, 1, EPI_V,   2, 3>, cudaFuncAttributeMaxDynamicSharedMemorySize, SM_1T);
    cudaFuncSetAttribute(gemm_kernel<2048, 1, EPI_PV,  2, 3>, cudaFuncAttributeMaxDynamicSharedMemorySize, SM_1T);
    cudaFuncSetAttribute(gemm_kernel<1024, 2, EPI_OUT, 2, 3>, cudaFuncAttributeMaxDynamicSharedMemorySize, SM_2T);
    cudaFuncSetAttribute(score_kernel, cudaFuncAttributeMaxDynamicSharedMemorySize, SM_SC);
    cudaFuncSetAttribute(trv_kernel,   cudaFuncAttributeMaxDynamicSharedMemorySize, SMT);

    split_x_kernel<<<4096, 256>>>(x);
    trw_kernel<<<dim3(32, 32, 4), 256>>>(wq, wk, wv, wo);

    gemm_kernel<1024, 3, EPI_QK, 2, 2><<<dim3(8, 32, 2), 256, SM_QK>>>(nullptr);
    gemm_kernel<1024, 1, EPI_V,  2, 3><<<dim3(8, 32, 1), 256, SM_1T>>>(nullptr);

    trv_kernel<<<dim3(16, 16), 256, SMT>>>();
    redc_kernel<<<1, 1024>>>();

    score_kernel<<<dim3(4, 16, 16), 256, SM_SC>>>();
    gemm_kernel<2048, 1, EPI_PV, 2, 3><<<dim3(1, 16, 16), 256, SM_1T>>>(nullptr);
    gemm_kernel<1024, 2, EPI_OUT, 2, 3><<<dim3(8, 32, 1), 256, SM_2T>>>(out);
}

// round 11
// speedup vs baseline: 1.2441x; 1.0971x over previous
#include <cuda_runtime.h>
#include <cuda_fp16.h>
#include <cstdint>

// ---------------------------------------------------------------------------
// B=2,S=2048,D=1024,H=16,HD=64, scale=32. softmax over batch (B=2) ==
//   P     = sigmoid((Q0K0^T - Q1K1^T)/32)   per head [2048x2048]
//   vals0 = P @ V0 ;  vals1 = colsum(V1) - P @ V1
// fp16 mma.sync m16n8k16 NT GEMMs; hi/lo split planes:
//   Q/K proj, score: 3-term | V proj, PV, out: 1-term
// ---------------------------------------------------------------------------

__device__ __align__(128) __half g_xhi[4096 * 1024];
__device__ __align__(128) __half g_xlo[4096 * 1024];
__device__ __align__(128) __half g_wThi[4 * 1024 * 1024];   // [z][n][k]
__device__ __align__(128) __half g_wTlo[4 * 1024 * 1024];
__device__ __align__(128) __half g_Qhi[16 * 2048 * 128];    // [h][s][b*64+d]
__device__ __align__(128) __half g_Qlo[16 * 2048 * 128];
__device__ __align__(128) __half g_Khi[16 * 2048 * 128];    // K1 negated
__device__ __align__(128) __half g_Klo[16 * 2048 * 128];
__device__ __align__(128) __half g_V16[16 * 2048 * 128];    // fp16 V [h][s][b*64+d]
__device__ __align__(128) __half g_Vthi[16 * 128 * 2048];   // [h][b*64+d][s]
__device__ __align__(128) __half g_P[(size_t)16 * 2048 * 2048];
__device__ __align__(128) __half g_Valshi[4096 * 1024];     // [b*2048+q][h*64+d]
__device__ float g_ColPart[16 * 16 * 64];
__device__ float g_Colsum[16 * 64];

#define SSTR   40                 // halfs per smem row, 32-K chunks (+8 pad)
#define PLANEH (128 * SSTR)       // 5120 halfs / 10240 B
#define ASTR   136                // halfs per row for resident 128-K planes

// ---------------------------------------------------------------------------
static __device__ __forceinline__ void cpa16(const __half* dst_smem, const void* src) {
    uint32_t d = (uint32_t)__cvta_generic_to_shared(dst_smem);
    asm volatile("cp.async.cg.shared.global [%0], [%1], 16;" :: "r"(d), "l"(src));
}
static __device__ __forceinline__ void ldm4(uint32_t r[4], const __half* p) {
    uint32_t a = (uint32_t)__cvta_generic_to_shared(p);
    asm volatile("ldmatrix.sync.aligned.m8n8.x4.shared.b16 {%0,%1,%2,%3}, [%4];"
                 : "=r"(r[0]), "=r"(r[1]), "=r"(r[2]), "=r"(r[3]) : "r"(a));
}
static __device__ __forceinline__ void mma16816(float c[4], const uint32_t a[4],
                                                uint32_t b0, uint32_t b1) {
    asm volatile(
        "mma.sync.aligned.m16n8k16.row.col.f32.f16.f16.f32 "
        "{%0,%1,%2,%3}, {%4,%5,%6,%7}, {%8,%9}, {%0,%1,%2,%3};"
        : "+f"(c[0]), "+f"(c[1]), "+f"(c[2]), "+f"(c[3])
        : "r"(a[0]), "r"(a[1]), "r"(a[2]), "r"(a[3]), "r"(b0), "r"(b1));
}
static __device__ __forceinline__ void splitstore(__half* hp, __half* lp,
                                                  float v0, float v1) {
    __half h0 = __float2half_rn(v0), h1 = __float2half_rn(v1);
    *(__half2*)hp = __halves2half2(h0, h1);
    *(__half2*)lp = __halves2half2(__float2half_rn(v0 - __half2float(h0)),
                                   __float2half_rn(v1 - __half2float(h1)));
}

enum { EPI_QK = 0, EPI_V, EPI_PV, EPI_OUT };

// ---------------------------------------------------------------------------
// 128x128 NT GEMM, fp16 mma + ldmatrix, NSTG-stage cp.async, fused epilogue.
// NTERM=3: Ahi*Bhi + Alo*Bhi + Ahi*Blo ; NTERM=2: A*(Bhi+Blo) ; NTERM=1: A*Bhi
// B-hi fragments are loaded once and reused across terms.
// ---------------------------------------------------------------------------
template <int KTOT, int NTERM, int EPI, int OCC, int NSTG>
__global__ __launch_bounds__(256, OCC) void gemm_kernel(float* outp)
{
    extern __shared__ __align__(128) __half sm[];
    const int NA = (NTERM == 3) ? 2 : 1;
    const int NB = (NTERM >= 2) ? 2 : 1;
    const int NT = NA + NB;

    const int tid = threadIdx.x, warp = tid >> 5, lane = tid & 31;
    const int wm = (warp & 3) * 32, wn = (warp >> 2) * 64;
    const int m0 = blockIdx.y * 128, n0 = blockIdx.x * 128, z = blockIdx.z;

    const __half *Ahi, *Alo = nullptr, *Bhi, *Blo = nullptr;
    int lda, ldb;
    if (EPI == EPI_QK) {
        Ahi = g_xhi; Alo = g_xlo; lda = 1024;
        Bhi = g_wThi + (size_t)z * 1048576; Blo = g_wTlo + (size_t)z * 1048576; ldb = 1024;
    } else if (EPI == EPI_V) {
        Ahi = g_xhi; lda = 1024;
        Bhi = g_wThi + (size_t)2 * 1048576; ldb = 1024;
    } else if (EPI == EPI_PV) {
        Ahi = g_P + (size_t)z * 2048 * 2048; lda = 2048;
        Bhi = g_Vthi + (size_t)z * 128 * 2048; ldb = 2048;
    } else {
        Ahi = g_Valshi; lda = 1024;
        Bhi = g_wThi + (size_t)3 * 1048576; ldb = 1024;
    }

    auto plane = [&](int st, int pl) -> __half* { return sm + (st * NT + pl) * PLANEH; };

    auto load_stage = [&](int ch) {
        const int st = ch % NSTG, k0 = ch * 32;
#pragma unroll
        for (int r = 0; r < 2; ++r) {
            const int idx = tid + r * 256;
            const int row = idx >> 2, col = (idx & 3) * 8;
            cpa16(plane(st, 0) + row * SSTR + col, Ahi + (size_t)(m0 + row) * lda + k0 + col);
            if (NA == 2)
                cpa16(plane(st, 1) + row * SSTR + col, Alo + (size_t)(m0 + row) * lda + k0 + col);
            cpa16(plane(st, NA) + row * SSTR + col, Bhi + (size_t)(n0 + row) * ldb + k0 + col);
            if (NB == 2)
                cpa16(plane(st, NA + 1) + row * SSTR + col, Blo + (size_t)(n0 + row) * ldb + k0 + col);
        }
        asm volatile("cp.async.commit_group;" ::: "memory");
    };

    float c[2][8][4] = {};
    const int nCh = KTOT / 32;
    load_stage(0);
    if (NSTG == 3 && nCh > 1) load_stage(1);

    const int lrow = lane & 15, lkh = (lane >> 4) * 8;

    for (int ch = 0; ch < nCh; ++ch) {
        if (NSTG == 3) {
            if (ch + 1 < nCh) asm volatile("cp.async.wait_group 1;" ::: "memory");
            else              asm volatile("cp.async.wait_group 0;" ::: "memory");
            __syncthreads();
            if (ch + 2 < nCh) load_stage(ch + 2);
        } else {
            if (ch + 1 < nCh) {
                __syncthreads();
                load_stage(ch + 1);
                asm volatile("cp.async.wait_group 1;" ::: "memory");
            } else {
                asm volatile("cp.async.wait_group 0;" ::: "memory");
            }
            __syncthreads();
        }
        const int buf = ch % NSTG;

#pragma unroll
        for (int s = 0; s < 2; ++s) {
            const int ks = s * 16;
            uint32_t a[2][2][4];
#pragma unroll
            for (int pa = 0; pa < NA; ++pa)
#pragma unroll
                for (int mt = 0; mt < 2; ++mt)
                    ldm4(a[pa][mt], plane(buf, pa) + (wm + mt * 16 + lrow) * SSTR + ks + lkh);

            // B-hi fragments: load once, reuse for term 1 and (NA==2) term 2
            uint32_t bh[4][4];
#pragma unroll
            for (int np = 0; np < 4; ++np) {
                ldm4(bh[np], plane(buf, NA) + (wn + np * 16 + lrow) * SSTR + ks + lkh);
#pragma unroll
                for (int mt = 0; mt < 2; ++mt) {
                    mma16816(c[mt][2 * np],     a[0][mt], bh[np][0], bh[np][2]);
                    mma16816(c[mt][2 * np + 1], a[0][mt], bh[np][1], bh[np][3]);
                }
            }
            if (NA == 2) {
#pragma unroll
                for (int np = 0; np < 4; ++np)
#pragma unroll
                    for (int mt = 0; mt < 2; ++mt) {
                        mma16816(c[mt][2 * np],     a[1][mt], bh[np][0], bh[np][2]);
                        mma16816(c[mt][2 * np + 1], a[1][mt], bh[np][1], bh[np][3]);
                    }
            }
            if (NB == 2) {
#pragma unroll
                for (int np = 0; np < 4; ++np) {
                    uint32_t bl[4];
                    ldm4(bl, plane(buf, NA + 1) + (wn + np * 16 + lrow) * SSTR + ks + lkh);
#pragma unroll
                    for (int mt = 0; mt < 2; ++mt) {
                        mma16816(c[mt][2 * np],     a[0][mt], bl[0], bl[2]);
                        mma16816(c[mt][2 * np + 1], a[0][mt], bl[1], bl[3]);
                    }
                }
            }
        }
    }

    // ---- epilogue: m = m0+wm+mt*16+lane/4+p*8 ; n = n0+wn+nt*8+(lane%4)*2 ----
#pragma unroll
    for (int mt = 0; mt < 2; ++mt)
#pragma unroll
        for (int nt = 0; nt < 8; ++nt)
#pragma unroll
            for (int p = 0; p < 2; ++p) {
                const int m = m0 + wm + mt * 16 + (lane >> 2) + p * 8;
                const int nl = wn + nt * 8 + (lane & 3) * 2;
                float v0 = c[mt][nt][2 * p], v1 = c[mt][nt][2 * p + 1];

                if (EPI == EPI_QK) {
                    const int b = m >> 11, s = m & 2047;
                    const int n = n0 + nl, h = n >> 6, d = n & 63;
                    const size_t base = ((size_t)(h * 2048 + s)) * 128 + b * 64 + d;
                    if (z == 1 && b == 1) { v0 = -v0; v1 = -v1; }
                    __half* Dh = (z == 0) ? g_Qhi : g_Khi;
                    __half* Dl = (z == 0) ? g_Qlo : g_Klo;
                    splitstore(&Dh[base], &Dl[base], v0, v1);
                } else if (EPI == EPI_V) {
                    const int b = m >> 11, s = m & 2047;
                    const int n = n0 + nl, h = n >> 6, d = n & 63;
                    *(__half2*)&g_V16[((size_t)(h * 2048 + s)) * 128 + b * 64 + d] =
                        __floats2half2_rn(v0, v1);
                } else if (EPI == EPI_PV) {
                    const int b = nl >> 6, d = nl & 63;
                    if (b) {
                        v0 = g_Colsum[z * 64 + d]     - v0;
                        v1 = g_Colsum[z * 64 + d + 1] - v1;
                    }
                    *(__half2*)&g_Valshi[((size_t)(b * 2048 + m)) * 1024 + z * 64 + d] =
                        __floats2half2_rn(v0, v1);
                } else {
                    *(float2*)&outp[(size_t)m * 1024 + n0 + nl] = make_float2(v0, v1);
                }
            }
}

// ---------------------------------------------------------------------------
// Score: Q hi/lo resident in smem; stream K hi/lo 2-stage over 4 n-tiles.
// smem = 69632 + 40960 = 110592 B -> occupancy 2.
// P = sigmoid(S/32) via f16x2 ex2+rcp.  Grid (4, 16, 16) = (n-group, m, h).
// ---------------------------------------------------------------------------
__global__ __launch_bounds__(256, 2) void score_kernel()
{
    extern __shared__ __align__(128) __half sm[];
    __half* Aq[2] = { sm, sm + 128 * ASTR };
    __half* Bb    = sm + 2 * 128 * ASTR;
    auto bplane = [&](int st, int pl) -> __half* { return Bb + (st * 2 + pl) * PLANEH; };

    const int tid = threadIdx.x, warp = tid >> 5, lane = tid & 31;
    const int wm = (warp & 3) * 32, wn = (warp >> 2) * 64;
    const int h = blockIdx.z, m0 = blockIdx.y * 128, nb = blockIdx.x * 512;

    const __half* Qh = g_Qhi + (size_t)h * 2048 * 128 + (size_t)m0 * 128;
    const __half* Ql = g_Qlo + (size_t)h * 2048 * 128 + (size_t)m0 * 128;
    const __half* Kh = g_Khi + (size_t)h * 2048 * 128;
    const __half* Kl = g_Klo + (size_t)h * 2048 * 128;

    // resident A: 128x128 per plane (8 rounds x 16B x 2 planes)
#pragma unroll
    for (int r = 0; r < 8; ++r) {
        const int idx = tid + r * 256;
        const int row = idx >> 4, col = (idx & 15) * 8;
        cpa16(Aq[0] + row * ASTR + col, Qh + row * 128 + col);
        cpa16(Aq[1] + row * ASTR + col, Ql + row * 128 + col);
    }
    asm volatile("cp.async.commit_group;" ::: "memory");

    auto loadB = [&](int g) {
        const int st = g & 1, ntl = g >> 2, k0 = (g & 3) * 32;
#pragma unroll
        for (int r = 0; r < 2; ++r) {
            const int idx = tid + r * 256;
            const int row = idx >> 2, col = (idx & 3) * 8;
            const size_t src = (size_t)(nb + ntl * 128 + row) * 128 + k0 + col;
            cpa16(bplane(st, 0) + row * SSTR + col, Kh + src);
            cpa16(bplane(st, 1) + row * SSTR + col, Kl + src);
        }
        asm volatile("cp.async.commit_group;" ::: "memory");
    };

    loadB(0);
    float c[2][8][4] = {};
    const int lrow = lane & 15, lkh = (lane >> 4) * 8;
    const __half2 one2 = __float2half2_rn(1.0f);
    const float NK = -0.04508422f;   // -log2(e)/32

    const int G = 16;   // 4 n-tiles x 4 chunks
    for (int g = 0; g < G; ++g) {
        if (g + 1 < G) {
            __syncthreads();                  // compute(g-1) done with stage (g+1)&1
            loadB(g + 1);
            asm volatile("cp.async.wait_group 1;" ::: "memory");  // stage g ready
        } else {
            asm volatile("cp.async.wait_group 0;" ::: "memory");
        }
        __syncthreads();

        const int st = g & 1, ch = g & 3;
#pragma unroll
        for (int s = 0; s < 2; ++s) {
            const int kA = ch * 32 + s * 16 + lkh;
            const int ks = s * 16;
            uint32_t a[2][2][4];
#pragma unroll
            for (int pa = 0; pa < 2; ++pa)
#pragma unroll
                for (int mt = 0; mt < 2; ++mt)
                    ldm4(a[pa][mt], Aq[pa] + (wm + mt * 16 + lrow) * ASTR + kA);

            // K-hi fragments loaded once, reused for Q-hi and Q-lo terms
            uint32_t bh[4][4];
#pragma unroll
            for (int np = 0; np < 4; ++np) {
                ldm4(bh[np], bplane(st, 0) + (wn + np * 16 + lrow) * SSTR + ks + lkh);
#pragma unroll
                for (int mt = 0; mt < 2; ++mt) {
                    mma16816(c[mt][2 * np],     a[0][mt], bh[np][0], bh[np][2]);
                    mma16816(c[mt][2 * np + 1], a[0][mt], bh[np][1], bh[np][3]);
                }
            }
#pragma unroll
            for (int np = 0; np < 4; ++np)
#pragma unroll
                for (int mt = 0; mt < 2; ++mt) {
                    mma16816(c[mt][2 * np],     a[1][mt], bh[np][0], bh[np][2]);
                    mma16816(c[mt][2 * np + 1], a[1][mt], bh[np][1], bh[np][3]);
                }
#pragma unroll
            for (int np = 0; np < 4; ++np) {
                uint32_t bl[4];
                ldm4(bl, bplane(st, 1) + (wn + np * 16 + lrow) * SSTR + ks + lkh);
#pragma unroll
                for (int mt = 0; mt < 2; ++mt) {
                    mma16816(c[mt][2 * np],     a[0][mt], bl[0], bl[2]);
                    mma16816(c[mt][2 * np + 1], a[0][mt], bl[1], bl[3]);
                }
            }
        }

        if (ch == 3) {   // epilogue for finished n-tile
            const int ntl = g >> 2;
#pragma unroll
            for (int mt = 0; mt < 2; ++mt)
#pragma unroll
                for (int nt = 0; nt < 8; ++nt)
#pragma unroll
                    for (int p = 0; p < 2; ++p) {
                        const int m = m0 + wm + mt * 16 + (lane >> 2) + p * 8;
                        const int n = ntl * 128 + nb + wn + nt * 8 + (lane & 3) * 2;
                        __half2 m2 = __floats2half2_rn(c[mt][nt][2 * p] * NK,
                                                       c[mt][nt][2 * p + 1] * NK);
                        __half2 P2 = h2rcp(__hadd2(one2, h2exp2(m2)));
                        *(__half2*)&g_P[((size_t)h * 2048 + m) * 2048 + n] = P2;
                        c[mt][nt][2 * p] = 0.f; c[mt][nt][2 * p + 1] = 0.f;
                    }
        }
    }
}

// ---------------------------------------------------------------------------
// prep kernels
// ---------------------------------------------------------------------------
__global__ __launch_bounds__(256) void split_x_kernel(const float* __restrict__ x)
{
    const size_t i = ((size_t)blockIdx.x * 256 + threadIdx.x) * 4;
    float4 v = *(const float4*)(x + i);
    splitstore(&g_xhi[i],     &g_xlo[i],     v.x, v.y);
    splitstore(&g_xhi[i + 2], &g_xlo[i + 2], v.z, v.w);
}

__global__ __launch_bounds__(256) void trw_kernel(
    const float* __restrict__ w0, const float* __restrict__ w1,
    const float* __restrict__ w2, const float* __restrict__ w3)
{
    const float* W = (blockIdx.z == 0) ? w0 : (blockIdx.z == 1) ? w1
                     : (blockIdx.z == 2) ? w2 : w3;
    __shared__ float t[32][33];
    const int bx = blockIdx.x * 32, by = blockIdx.y * 32;
    const int tx = threadIdx.x & 31, ty8 = threadIdx.x >> 5;
#pragma unroll
    for (int s = 0; s < 4; ++s)
        t[ty8 + s * 8][tx] = W[(size_t)(by + ty8 + s * 8) * 1024 + bx + tx];
    __syncthreads();
    __half* Dh = g_wThi + (size_t)blockIdx.z * 1048576;
    __half* Dl = g_wTlo + (size_t)blockIdx.z * 1048576;
#pragma unroll
    for (int s = 0; s < 4; ++s) {
        const int ty = ty8 + s * 8;
        const float v = t[tx][ty];
        const size_t o = (size_t)(bx + ty) * 1024 + by + tx;
        __half h = __float2half_rn(v);
        Dh[o] = h;
        Dl[o] = __float2half_rn(v - __half2float(h));
    }
}

// transpose V per (head, 128-s-chunk) + deterministic colsum partials of V1
__global__ __launch_bounds__(256) void trv_kernel()
{
    extern __shared__ float tl[];   // [128][129]
    const int sc = blockIdx.x, h = blockIdx.y;
    const int s0 = sc * 128;
    const __half* V = g_V16 + ((size_t)h * 2048 + s0) * 128;

    for (int i = threadIdx.x; i < 128 * 128; i += 256)
        tl[(i >> 7) * 129 + (i & 127)] = __half2float(V[i]);
    __syncthreads();

    if (threadIdx.x < 64) {
        float acc = 0.f;
        for (int s = 0; s < 128; ++s) acc += tl[s * 129 + 64 + threadIdx.x];
        g_ColPart[((size_t)h * 16 + sc) * 64 + threadIdx.x] = acc;
    }

    const int dp = threadIdx.x & 127, seg = threadIdx.x >> 7;
    __half* Th = g_Vthi + ((size_t)h * 128 + dp) * 2048 + s0 + seg * 64;
#pragma unroll 8
    for (int j = 0; j < 64; ++j)
        Th[j] = __float2half_rn(tl[(seg * 64 + j) * 129 + dp]);
}

__global__ void redc_kernel()
{
    const int t = threadIdx.x;   // 1024 = 16h * 64d
    const int h = t >> 6, d = t & 63;
    float a = 0.f;
    for (int sc = 0; sc < 16; ++sc)
        a += g_ColPart[((size_t)h * 16 + sc) * 64 + d];
    g_Colsum[t] = a;
}

// ---------------------------------------------------------------------------
extern "C" void kernel_launch(void* const* d_in, const int* in_sizes, int n_in,
                              void* d_out, int out_size)
{
    const float* x  = (const float*)d_in[0];
    const float* wq = (const float*)d_in[1];
    const float* wk = (const float*)d_in[2];
    const float* wv = (const float*)d_in[3];
    const float* wo = (const float*)d_in[4];
    float* out = (float*)d_out;

    const int PB    = PLANEH * 2;                         // 10240 B / plane
    const int SM_QK = 2 * 4 * PB;                         //  81920 (3-term, 2-stage)
    const int SM_1T = 3 * 2 * PB;                         //  61440 (1-term, 3-stage)
    const int SM_SC = 2 * 128 * ASTR * 2 + 2 * 2 * PB;    // 110592 (score, 2-stage)
    const int SMT   = 128 * 129 * 4;                      //  66048

    cudaFuncSetAttribute(gemm_kernel<1024, 3, EPI_QK,  2, 2>, cudaFuncAttributeMaxDynamicSharedMemorySize, SM_QK);
    cudaFuncSetAttribute(gemm_kernel<1024, 1, EPI_V,   2, 3>, cudaFuncAttributeMaxDynamicSharedMemorySize, SM_1T);
    cudaFuncSetAttribute(gemm_kernel<2048, 1, EPI_PV,  2, 3>, cudaFuncAttributeMaxDynamicSharedMemorySize, SM_1T);
    cudaFuncSetAttribute(gemm_kernel<1024, 1, EPI_OUT, 2, 3>, cudaFuncAttributeMaxDynamicSharedMemorySize, SM_1T);
    cudaFuncSetAttribute(score_kernel, cudaFuncAttributeMaxDynamicSharedMemorySize, SM_SC);
    cudaFuncSetAttribute(trv_kernel,   cudaFuncAttributeMaxDynamicSharedMemorySize, SMT);

    split_x_kernel<<<4096, 256>>>(x);
    trw_kernel<<<dim3(32, 32, 4), 256>>>(wq, wk, wv, wo);

    gemm_kernel<1024, 3, EPI_QK, 2, 2><<<dim3(8, 32, 2), 256, SM_QK>>>(nullptr);
    gemm_kernel<1024, 1, EPI_V,  2, 3><<<dim3(8, 32, 1), 256, SM_1T>>>(nullptr);

    trv_kernel<<<dim3(16, 16), 256, SMT>>>();
    redc_kernel<<<1, 1024>>>();

    score_kernel<<<dim3(4, 16, 16), 256, SM_SC>>>();
    gemm_kernel<2048, 1, EPI_PV, 2, 3><<<dim3(1, 16, 16), 256, SM_1T>>>(nullptr);
    gemm_kernel<1024, 1, EPI_OUT, 2, 3><<<dim3(8, 32, 1), 256, SM_1T>>>(out);
}